// round 12
// baseline (speedup 1.0000x reference)
#include <cuda_runtime.h>
#include <cuda_bf16.h>
#include <cuda_fp16.h>
#include <cstdint>

#define NN 50000
#define NE 800000
#define DD 128
#define ND (NN * DD)          // 6,400,000
#define LSLOPE 0.01f
#define BN_EPS 1e-5f
#define SCAN_B 196            // ceil(NN/256)

// ---------------- scratch (device globals; no allocation allowed) ----------
__device__ float g_embs[4 * ND];       // e after layer-1 residual (written by gemm L1)
__device__ __half2 g_Hh[2 * ND];       // H (fp16) all layers, 4*ND halves
__device__ float g_Y[4 * ND];
__device__ float g_csrc[4 * NN];
__device__ float g_cdst[4 * NN];
__device__ int   g_cnt_in[4 * NN];
__device__ int   g_cnt_out[4 * NN];
__device__ int   g_cur[4 * NN];
__device__ int   g_off[4 * (NN + 1)];
__device__ int   g_csr[4 * NE];
__device__ int   g_bsum[4 * 256];      // per-block sums for scan
__device__ int   g_bpre[4 * 256];      // exclusive prefix of block sums
__device__ float g_rels[4 * DD];
__device__ float g_stats[4 * 2 * DD];
__device__ uint32_t g_Bh[3 * 128 * 64];
__device__ uint32_t g_Bl[3 * 128 * 64];

// ---------------- CSR build ------------------------------------------------
__global__ void k_hist(const int* __restrict__ e0, const int* __restrict__ e1,
                       const int* __restrict__ e2, const int* __restrict__ e3) {
    int gid = blockIdx.x * 256 + threadIdx.x;
    if (gid >= 4 * NE) return;
    int t = gid / NE;
    int e = gid - t * NE;
    const int* ei = (t == 0) ? e0 : (t == 1) ? e1 : (t == 2) ? e2 : e3;
    atomicAdd(&g_cnt_out[t * NN + ei[e]], 1);
    atomicAdd(&g_cnt_in[t * NN + ei[NE + e]], 1);
}
// pass 1: per-block sums of cnt_in
__global__ void k_scan1() {
    const int t = blockIdx.y;
    int i = blockIdx.x * 256 + threadIdx.x;
    int v = (i < NN) ? g_cnt_in[t * NN + i] : 0;
    __shared__ int sh[256];
    sh[threadIdx.x] = v;
    __syncthreads();
    for (int ofs = 128; ofs > 0; ofs >>= 1) {
        if (threadIdx.x < ofs) sh[threadIdx.x] += sh[threadIdx.x + ofs];
        __syncthreads();
    }
    if (threadIdx.x == 0) g_bsum[t * 256 + blockIdx.x] = sh[0];
}
// pass 2: exclusive prefix of block sums (one block per type)
__global__ void k_scan2() {
    const int t = blockIdx.x;
    int tid = threadIdx.x;
    int v = (tid < SCAN_B) ? g_bsum[t * 256 + tid] : 0;
    __shared__ int sh[256];
    sh[tid] = v;
    __syncthreads();
    int val = v;
    for (int ofs = 1; ofs < 256; ofs <<= 1) {
        int add = (tid >= ofs) ? sh[tid - ofs] : 0;
        __syncthreads();
        val += add;
        sh[tid] = val;
        __syncthreads();
    }
    g_bpre[t * 256 + tid] = val - v;   // exclusive
    if (tid == 255) g_off[t * (NN + 1) + NN] = val;
}
// pass 3: local exclusive scan + block prefix -> offsets
__global__ void k_scan3() {
    const int t = blockIdx.y;
    int tid = threadIdx.x;
    int i = blockIdx.x * 256 + tid;
    int v = (i < NN) ? g_cnt_in[t * NN + i] : 0;
    __shared__ int sh[256];
    sh[tid] = v;
    __syncthreads();
    int val = v;
    for (int ofs = 1; ofs < 256; ofs <<= 1) {
        int add = (tid >= ofs) ? sh[tid - ofs] : 0;
        __syncthreads();
        val += add;
        sh[tid] = val;
        __syncthreads();
    }
    if (i < NN)
        g_off[t * (NN + 1) + i] = g_bpre[t * 256 + blockIdx.x] + val - v;
}
__global__ void k_c() {
    int gid = blockIdx.x * 256 + threadIdx.x;
    if (gid >= 4 * NN) return;
    int t = gid / NN, v = gid - t * NN;
    int dout = g_cnt_out[gid];
    int din  = g_cnt_in[gid];
    g_csrc[gid] = dout > 0 ? rsqrtf((float)dout) : 1.0f;
    g_cdst[gid] = din  > 0 ? rsqrtf((float)din)  : 1.0f;
    g_cur[gid]  = g_off[t * (NN + 1) + v];
}
__global__ void k_fill(const int* __restrict__ e0, const int* __restrict__ e1,
                       const int* __restrict__ e2, const int* __restrict__ e3) {
    int gid = blockIdx.x * 256 + threadIdx.x;
    if (gid >= 4 * NE) return;
    int t = gid / NE;
    int e = gid - t * NE;
    const int* ei = (t == 0) ? e0 : (t == 1) ? e1 : (t == 2) ? e2 : e3;
    int s = ei[e], d = ei[NE + e];
    int pos = atomicAdd(&g_cur[t * NN + d], 1);
    g_csr[t * NE + pos] = s;
}

// ---------------- misc init ------------------------------------------------
__global__ void k_relinit(const float* __restrict__ r0, const float* __restrict__ r1,
                          const float* __restrict__ r2, const float* __restrict__ r3) {
    int tid = threadIdx.x;
    if (tid >= 512) return;
    int t = tid >> 7, d = tid & 127;
    const float* r = (t == 0) ? r0 : (t == 1) ? r1 : (t == 2) ? r2 : r3;
    g_rels[t * DD + d] = r[d];
}

// ---------------- W pre-split (all 3 layers): B[l][n][kp] -----------------
__global__ void k_prepw(const float* __restrict__ gW) {
    int layer = blockIdx.y;
    int slot = blockIdx.x * 256 + threadIdx.x;
    if (slot >= 128 * 64) return;
    const float* W = gW + layer * DD * DD;
    int n  = slot >> 6;
    int kp = slot & 63;
    uint32_t hw = 0, lw = 0;
#pragma unroll
    for (int s = 0; s < 2; s++) {
        float w = W[(kp * 2 + s) * 128 + n];
        __nv_bfloat16 hi = __float2bfloat16(w);
        float rem = w - __bfloat162float(hi);
        __nv_bfloat16 lo = __float2bfloat16(rem);
        hw |= (uint32_t)__bfloat16_as_ushort(hi) << (16 * s);
        lw |= (uint32_t)__bfloat16_as_ushort(lo) << (16 * s);
    }
    g_Bh[layer * 8192 + slot] = hw;
    g_Bl[layer * 8192 + slot] = lw;
}

// ---------------- bf16x3 mma.sync GEMM with fused BN/residual A-load ------
#define MMA_BF16(c, a, b) asm volatile( \
    "mma.sync.aligned.m16n8k16.row.col.f32.bf16.bf16.f32 " \
    "{%0,%1,%2,%3}, {%4,%5,%6,%7}, {%8,%9}, {%0,%1,%2,%3};" \
    : "+f"((c)[0]), "+f"((c)[1]), "+f"((c)[2]), "+f"((c)[3]) \
    : "r"((a)[0]), "r"((a)[1]), "r"((a)[2]), "r"((a)[3]), "r"((b)[0]), "r"((b)[1]))

__global__ void __launch_bounds__(256) k_gemm(int layer, const float* __restrict__ feat,
                                              const float* __restrict__ gamma,
                                              const float* __restrict__ beta) {
    __shared__ uint32_t As_h[128][20];
    __shared__ uint32_t As_l[128][20];
    __shared__ uint32_t Bs_h[128][20];
    __shared__ uint32_t Bs_l[128][20];
    __shared__ float srel[128];
    __shared__ float s_a[128];
    __shared__ float s_sh[128];
    const int tid  = threadIdx.x;
    const int wid  = tid >> 5;
    const int lane = tid & 31;
    const int t    = blockIdx.y;
    const int rb   = blockIdx.x * 128;
    const float* Xsrc = (layer < 2) ? feat : (g_embs + (long)t * ND);
    float* Xwb = g_embs + (long)t * ND;
    const float* Yt = g_Y + (long)t * ND;
    const float* cs = g_csrc + t * NN;
    const uint32_t* Bhb = g_Bh + layer * 8192;
    const uint32_t* Blb = g_Bl + layer * 8192;
    if (tid < 128) {
        srel[tid] = g_rels[t * DD + tid];
        if (layer > 0) {
            float mu  = g_stats[t * 256 + tid] * (1.0f / NN);
            float var = g_stats[t * 256 + 128 + tid] * (1.0f / NN) - mu * mu;
            float a = rsqrtf(var + BN_EPS) * gamma[tid];
            s_a[tid]  = a;
            s_sh[tid] = beta[tid] - mu * a;
        }
    }

    float acc[16][4];
#pragma unroll
    for (int nb = 0; nb < 16; nb++)
#pragma unroll
        for (int j = 0; j < 4; j++) acc[nb][j] = 0.f;

    const int r0 = wid * 16 + (lane >> 2);
    const int kq = lane & 3;

    for (int kc = 0; kc < 4; kc++) {
        __syncthreads();  // also guards srel/s_a/s_sh on first iter
#pragma unroll
        for (int u = 0; u < 4; u++) {
            int slot = tid + u * 256;
            int row  = slot >> 3;
            int c4   = (slot & 7) * 4;
            int grow = rb + row;
            uint32_t h0 = 0, h1 = 0, l0 = 0, l1 = 0;
            if (grow < NN) {
                float c = cs[grow];
                float4 v = *(const float4*)(Xsrc + (long)grow * 128 + kc * 32 + c4);
                if (layer > 0) {   // fused BN + leaky + residual
                    float4 yv = *(const float4*)(Yt + (long)grow * 128 + kc * 32 + c4);
#pragma unroll
                    for (int uu = 0; uu < 4; uu++) {
                        int k = kc * 32 + c4 + uu;
                        float h = (&yv.x)[uu] * s_a[k] + s_sh[k];
                        h = h > 0.f ? h : LSLOPE * h;
                        (&v.x)[uu] += h;
                    }
                    if (layer == 1)
                        *(float4*)(Xwb + (long)grow * 128 + kc * 32 + c4) = v;
                }
                float f[4] = {v.x, v.y, v.z, v.w};
                uint32_t hw[2], lw[2];
#pragma unroll
                for (int jp = 0; jp < 2; jp++) {
                    uint32_t hcur = 0, lcur = 0;
#pragma unroll
                    for (int s = 0; s < 2; s++) {
                        float val = f[jp * 2 + s] * c * srel[kc * 32 + c4 + jp * 2 + s];
                        __nv_bfloat16 hi = __float2bfloat16(val);
                        float rem = val - __bfloat162float(hi);
                        __nv_bfloat16 lo = __float2bfloat16(rem);
                        hcur |= (uint32_t)__bfloat16_as_ushort(hi) << (16 * s);
                        lcur |= (uint32_t)__bfloat16_as_ushort(lo) << (16 * s);
                    }
                    hw[jp] = hcur; lw[jp] = lcur;
                }
                h0 = hw[0]; h1 = hw[1]; l0 = lw[0]; l1 = lw[1];
            }
            int kp = c4 >> 1;
            As_h[row][kp] = h0; As_h[row][kp + 1] = h1;
            As_l[row][kp] = l0; As_l[row][kp + 1] = l1;
        }
#pragma unroll
        for (int u = 0; u < 8; u++) {
            int slot = tid + u * 256;
            int n  = slot >> 4;
            int kp = slot & 15;
            Bs_h[n][kp] = Bhb[n * 64 + kc * 16 + kp];
            Bs_l[n][kp] = Blb[n * 64 + kc * 16 + kp];
        }
        __syncthreads();
#pragma unroll
        for (int s = 0; s < 2; s++) {
            uint32_t ah[4], al[4];
            ah[0] = As_h[r0][s * 8 + kq];
            ah[1] = As_h[r0 + 8][s * 8 + kq];
            ah[2] = As_h[r0][s * 8 + 4 + kq];
            ah[3] = As_h[r0 + 8][s * 8 + 4 + kq];
            al[0] = As_l[r0][s * 8 + kq];
            al[1] = As_l[r0 + 8][s * 8 + kq];
            al[2] = As_l[r0][s * 8 + 4 + kq];
            al[3] = As_l[r0 + 8][s * 8 + 4 + kq];
#pragma unroll
            for (int nb = 0; nb < 16; nb++) {
                int n = nb * 8 + (lane >> 2);
                uint32_t bh[2], bl[2];
                bh[0] = Bs_h[n][s * 8 + kq];
                bh[1] = Bs_h[n][s * 8 + 4 + kq];
                bl[0] = Bs_l[n][s * 8 + kq];
                bl[1] = Bs_l[n][s * 8 + 4 + kq];
                MMA_BF16(acc[nb], ah, bh);
                MMA_BF16(acc[nb], ah, bl);
                MMA_BF16(acc[nb], al, bh);
            }
        }
    }
    int row_a = rb + r0;
    int row_b = row_a + 8;
    int coff  = (lane & 3) * 2;
    __half2* Hh = g_Hh + (long)t * (ND / 2);
#pragma unroll
    for (int nb = 0; nb < 16; nb++) {
        int h2i = (nb * 8 + coff) >> 1;
        if (row_a < NN)
            Hh[(long)row_a * 64 + h2i] = __floats2half2_rn(acc[nb][0], acc[nb][1]);
        if (row_b < NN)
            Hh[(long)row_b * 64 + h2i] = __floats2half2_rn(acc[nb][2], acc[nb][3]);
    }
}

// ---------------- CSR gather (fp16 H), barrier-free warps, MLP=4 ----------
__global__ void __launch_bounds__(256) k_gather(const float* __restrict__ b,
                                                float* ydst) {
    const int t = blockIdx.y;
    int gid  = blockIdx.x * 256 + threadIdx.x;
    int w    = gid >> 5;
    int lane = gid & 31;
    if (w >= NN) return;
    float* ybase = (ydst == nullptr) ? g_Y : ydst;
    const int* csr = g_csr + (long)t * NE;
    const uint2* Hh = (const uint2*)(g_Hh + (long)t * (ND / 2));
    int beg = g_off[t * (NN + 1) + w];
    int end = g_off[t * (NN + 1) + w + 1];
    float4 a0 = make_float4(0.f, 0.f, 0.f, 0.f);
    float4 a1 = make_float4(0.f, 0.f, 0.f, 0.f);
    float4 a2 = make_float4(0.f, 0.f, 0.f, 0.f);
    float4 a3 = make_float4(0.f, 0.f, 0.f, 0.f);
    for (int base = beg; base < end; base += 32) {
        int idx = base + lane;
        int s_l = (idx < end) ? csr[idx] : 0;
        int cnt = min(32, end - base);
        int j = 0;
        for (; j + 3 < cnt; j += 4) {
            int s0 = __shfl_sync(0xffffffffu, s_l, j);
            int s1 = __shfl_sync(0xffffffffu, s_l, j + 1);
            int s2 = __shfl_sync(0xffffffffu, s_l, j + 2);
            int s3 = __shfl_sync(0xffffffffu, s_l, j + 3);
            uint2 u0 = Hh[(long)s0 * 32 + lane];
            uint2 u1 = Hh[(long)s1 * 32 + lane];
            uint2 u2 = Hh[(long)s2 * 32 + lane];
            uint2 u3 = Hh[(long)s3 * 32 + lane];
            float2 f0 = __half22float2(*(__half2*)&u0.x);
            float2 f1 = __half22float2(*(__half2*)&u0.y);
            a0.x += f0.x; a0.y += f0.y; a0.z += f1.x; a0.w += f1.y;
            f0 = __half22float2(*(__half2*)&u1.x);
            f1 = __half22float2(*(__half2*)&u1.y);
            a1.x += f0.x; a1.y += f0.y; a1.z += f1.x; a1.w += f1.y;
            f0 = __half22float2(*(__half2*)&u2.x);
            f1 = __half22float2(*(__half2*)&u2.y);
            a2.x += f0.x; a2.y += f0.y; a2.z += f1.x; a2.w += f1.y;
            f0 = __half22float2(*(__half2*)&u3.x);
            f1 = __half22float2(*(__half2*)&u3.y);
            a3.x += f0.x; a3.y += f0.y; a3.z += f1.x; a3.w += f1.y;
        }
        for (; j < cnt; j++) {
            int s0 = __shfl_sync(0xffffffffu, s_l, j);
            uint2 u0 = Hh[(long)s0 * 32 + lane];
            float2 f0 = __half22float2(*(__half2*)&u0.x);
            float2 f1 = __half22float2(*(__half2*)&u0.y);
            a0.x += f0.x; a0.y += f0.y; a0.z += f1.x; a0.w += f1.y;
        }
    }
    float cd = g_cdst[t * NN + w];
    float4 bb = *(const float4*)(b + lane * 4);
    float4 r;
    r.x = ((a0.x + a1.x) + (a2.x + a3.x)) * cd + bb.x;
    r.y = ((a0.y + a1.y) + (a2.y + a3.y)) * cd + bb.y;
    r.z = ((a0.z + a1.z) + (a2.z + a3.z)) * cd + bb.z;
    r.w = ((a0.w + a1.w) + (a2.w + a3.w)) * cd + bb.w;
    *(float4*)(ybase + (long)t * ND + (long)w * 128 + lane * 4) = r;
}

// ---------------- BN column stats over g_Y (batched over types) -----------
__global__ void k_stats() {
    const int t = blockIdx.y;
    const float* Y = g_Y + (long)t * ND;
    int tid  = threadIdx.x;
    int col  = tid & 127;
    int base = blockIdx.x * 256;
    int end  = min(base + 256, NN);
    float s = 0.f, s2 = 0.f;
    for (int r = base + (tid >> 7); r < end; r += 2) {
        float y = Y[(long)r * 128 + col];
        s += y;
        s2 += y * y;
    }
    __shared__ float sh[512];
    sh[tid] = s;
    sh[256 + tid] = s2;
    __syncthreads();
    if (tid < 128) {
        atomicAdd(&g_stats[t * 256 + col],       sh[tid] + sh[tid + 128]);
        atomicAdd(&g_stats[t * 256 + 128 + col], sh[256 + tid] + sh[256 + tid + 128]);
    }
}

// ---------------- relation vector updates ---------------------------------
__global__ void k_relupd(const float* __restrict__ Wr, const float* __restrict__ br) {
    const int t = blockIdx.x;
    __shared__ float sr[128];
    int d = threadIdx.x;
    sr[d] = g_rels[t * DD + d];
    __syncthreads();
    float s = br[d];
#pragma unroll
    for (int k = 0; k < 128; k++) s += sr[k] * Wr[d * 128 + k];
    g_rels[t * DD + d] = s;
}
__global__ void k_relout(const float* __restrict__ Wr, const float* __restrict__ br,
                         float* __restrict__ out) {
    const int t = blockIdx.x;
    __shared__ float sr[128];
    int d = threadIdx.x;
    sr[d] = g_rels[t * DD + d];
    __syncthreads();
    float s = br[d];
#pragma unroll
    for (int k = 0; k < 128; k++) s += sr[k] * Wr[d * 128 + k];
    out[t * DD + d] = s;
}

// ---------------- host orchestration --------------------------------------
extern "C" void kernel_launch(void* const* d_in, const int* in_sizes, int n_in,
                              void* d_out, int out_size) {
    const float* feat = (const float*)d_in[0];
    const float* r0 = (const float*)d_in[1];
    const float* r1 = (const float*)d_in[2];
    const float* r2 = (const float*)d_in[3];
    const float* r3 = (const float*)d_in[4];
    const int* e0 = (const int*)d_in[5];
    const int* e1 = (const int*)d_in[6];
    const int* e2 = (const int*)d_in[7];
    const int* e3 = (const int*)d_in[8];
    const float* gW  = (const float*)d_in[9];
    const float* gb  = (const float*)d_in[10];
    const float* bng = (const float*)d_in[11];
    const float* bnb = (const float*)d_in[12];
    const float* rW  = (const float*)d_in[13];
    const float* rb_ = (const float*)d_in[14];
    float* out = (float*)d_out;

    void *p_cnt_in = nullptr, *p_cnt_out = nullptr, *p_stats = nullptr;
    cudaGetSymbolAddress(&p_cnt_in, g_cnt_in);
    cudaGetSymbolAddress(&p_cnt_out, g_cnt_out);
    cudaGetSymbolAddress(&p_stats, g_stats);

    // setup
    cudaMemsetAsync(p_cnt_in, 0, 4 * NN * sizeof(int), 0);
    cudaMemsetAsync(p_cnt_out, 0, 4 * NN * sizeof(int), 0);
    k_hist<<<(4 * NE + 255) / 256, 256>>>(e0, e1, e2, e3);
    {
        dim3 g(SCAN_B, 4);
        k_scan1<<<g, 256>>>();
        k_scan2<<<4, 256>>>();
        k_scan3<<<g, 256>>>();
    }
    k_c<<<(4 * NN + 255) / 256, 256>>>();
    k_fill<<<(4 * NE + 255) / 256, 256>>>(e0, e1, e2, e3);
    k_relinit<<<1, 512>>>(r0, r1, r2, r3);
    {
        dim3 g(32, 3);
        k_prepw<<<g, 256>>>(gW);
    }

    const dim3 GEMM_G((NN + 127) / 128, 4);
    const dim3 GATH_G((NN * 32 + 255) / 256, 4);
    const dim3 STAT_G((NN + 255) / 256, 4);

    // conv 0
    k_gemm<<<GEMM_G, 256>>>(0, feat, nullptr, nullptr);
    k_relupd<<<4, 128>>>(rW + 0 * DD * DD, rb_ + 0 * DD);
    k_gather<<<GATH_G, 256>>>(gb + 0 * DD, nullptr);
    cudaMemsetAsync(p_stats, 0, 1024 * sizeof(float), 0);
    k_stats<<<STAT_G, 256>>>();
    // conv 1 (fuses BN0+residual; writes e_new to g_embs)
    k_gemm<<<GEMM_G, 256>>>(1, feat, bng + 0 * DD, bnb + 0 * DD);
    k_relupd<<<4, 128>>>(rW + 1 * DD * DD, rb_ + 1 * DD);
    k_gather<<<GATH_G, 256>>>(gb + 1 * DD, nullptr);
    cudaMemsetAsync(p_stats, 0, 1024 * sizeof(float), 0);
    k_stats<<<STAT_G, 256>>>();
    // conv 2 (fuses BN1+residual; reads g_embs; fp16 H -> gather to out)
    k_gemm<<<GEMM_G, 256>>>(2, feat, bng + 1 * DD, bnb + 1 * DD);
    k_relout<<<4, 128>>>(rW + 2 * DD * DD, rb_ + 2 * DD, out + 4L * ND);
    k_gather<<<GATH_G, 256>>>(gb + 2 * DD, out);
}

// round 13
// speedup vs baseline: 1.1345x; 1.1345x over previous
#include <cuda_runtime.h>
#include <cuda_bf16.h>
#include <cuda_fp16.h>
#include <cstdint>

#define NN 50000
#define NE 800000
#define DD 128
#define ND (NN * DD)          // 6,400,000
#define LSLOPE 0.01f
#define BN_EPS 1e-5f
#define SCAN_B 196            // ceil(NN/256)

// ---------------- scratch (device globals; no allocation allowed) ----------
__device__ float g_embs[4 * ND];       // e after layer-1 residual (written by gemm L1)
__device__ __half2 g_Hh[2 * ND];       // H (fp16) all layers, 4*ND halves
__device__ float g_Y[4 * ND];
__device__ float g_csrc[4 * NN];
__device__ float g_cdst[4 * NN];
__device__ int   g_cnt_in[4 * NN];
__device__ int   g_cnt_out[4 * NN];
__device__ int   g_cur[4 * NN];
__device__ int   g_off[4 * (NN + 1)];
__device__ int   g_csr[4 * NE];
__device__ int   g_bsum[4 * 256];
__device__ int   g_bpre[4 * 256];
__device__ float g_rels[4 * DD];
__device__ float g_stats[4 * 2 * DD];
__device__ uint32_t g_Bh[3 * 128 * 64];
__device__ uint32_t g_Bl[3 * 128 * 64];

// ---------------- CSR build ------------------------------------------------
__global__ void k_zero_hist() {
    int i = blockIdx.x * 256 + threadIdx.x;
    if (i < 4 * NN) { g_cnt_in[i] = 0; g_cnt_out[i] = 0; }
}
__global__ void k_hist(const int* __restrict__ e0, const int* __restrict__ e1,
                       const int* __restrict__ e2, const int* __restrict__ e3) {
    int gid = blockIdx.x * 256 + threadIdx.x;
    if (gid >= 4 * NE) return;
    int t = gid / NE;
    int e = gid - t * NE;
    const int* ei = (t == 0) ? e0 : (t == 1) ? e1 : (t == 2) ? e2 : e3;
    atomicAdd(&g_cnt_out[t * NN + ei[e]], 1);
    atomicAdd(&g_cnt_in[t * NN + ei[NE + e]], 1);
}
// pass 1: per-block sums of cnt_in
__global__ void k_scan1() {
    const int t = blockIdx.y;
    int i = blockIdx.x * 256 + threadIdx.x;
    int v = (i < NN) ? g_cnt_in[t * NN + i] : 0;
    __shared__ int sh[256];
    sh[threadIdx.x] = v;
    __syncthreads();
    for (int ofs = 128; ofs > 0; ofs >>= 1) {
        if (threadIdx.x < ofs) sh[threadIdx.x] += sh[threadIdx.x + ofs];
        __syncthreads();
    }
    if (threadIdx.x == 0) g_bsum[t * 256 + blockIdx.x] = sh[0];
}
// pass 2: exclusive prefix of block sums (one block per type)
__global__ void k_scan2() {
    const int t = blockIdx.x;
    int tid = threadIdx.x;
    int v = (tid < SCAN_B) ? g_bsum[t * 256 + tid] : 0;
    __shared__ int sh[256];
    sh[tid] = v;
    __syncthreads();
    int val = v;
    for (int ofs = 1; ofs < 256; ofs <<= 1) {
        int add = (tid >= ofs) ? sh[tid - ofs] : 0;
        __syncthreads();
        val += add;
        sh[tid] = val;
        __syncthreads();
    }
    g_bpre[t * 256 + tid] = val - v;   // exclusive
    if (tid == 255) g_off[t * (NN + 1) + NN] = val;
}
// pass 3: local exclusive scan + block prefix -> offsets
__global__ void k_scan3() {
    const int t = blockIdx.y;
    int tid = threadIdx.x;
    int i = blockIdx.x * 256 + tid;
    int v = (i < NN) ? g_cnt_in[t * NN + i] : 0;
    __shared__ int sh[256];
    sh[tid] = v;
    __syncthreads();
    int val = v;
    for (int ofs = 1; ofs < 256; ofs <<= 1) {
        int add = (tid >= ofs) ? sh[tid - ofs] : 0;
        __syncthreads();
        val += add;
        sh[tid] = val;
        __syncthreads();
    }
    if (i < NN)
        g_off[t * (NN + 1) + i] = g_bpre[t * 256 + blockIdx.x] + val - v;
}
__global__ void k_c() {
    int gid = blockIdx.x * 256 + threadIdx.x;
    if (gid >= 4 * NN) return;
    int t = gid / NN, v = gid - t * NN;
    int dout = g_cnt_out[gid];
    int din  = g_cnt_in[gid];
    g_csrc[gid] = dout > 0 ? rsqrtf((float)dout) : 1.0f;
    g_cdst[gid] = din  > 0 ? rsqrtf((float)din)  : 1.0f;
    g_cur[gid]  = g_off[t * (NN + 1) + v];
}
__global__ void k_fill(const int* __restrict__ e0, const int* __restrict__ e1,
                       const int* __restrict__ e2, const int* __restrict__ e3) {
    int gid = blockIdx.x * 256 + threadIdx.x;
    if (gid >= 4 * NE) return;
    int t = gid / NE;
    int e = gid - t * NE;
    const int* ei = (t == 0) ? e0 : (t == 1) ? e1 : (t == 2) ? e2 : e3;
    int s = ei[e], d = ei[NE + e];
    int pos = atomicAdd(&g_cur[t * NN + d], 1);
    g_csr[t * NE + pos] = s;
}

// ---------------- misc init ------------------------------------------------
__global__ void k_relinit(const float* __restrict__ r0, const float* __restrict__ r1,
                          const float* __restrict__ r2, const float* __restrict__ r3) {
    int tid = threadIdx.x;
    if (tid >= 512) return;
    int t = tid >> 7, d = tid & 127;
    const float* r = (t == 0) ? r0 : (t == 1) ? r1 : (t == 2) ? r2 : r3;
    g_rels[t * DD + d] = r[d];
}
__global__ void k_zero_stats() {
    int i = threadIdx.x;
    if (i < 1024) g_stats[i] = 0.f;
}

// ---------------- W pre-split (all 3 layers): B[l][n][kp] -----------------
__global__ void k_prepw(const float* __restrict__ gW) {
    int layer = blockIdx.y;
    int slot = blockIdx.x * 256 + threadIdx.x;
    if (slot >= 128 * 64) return;
    const float* W = gW + layer * DD * DD;
    int n  = slot >> 6;
    int kp = slot & 63;
    uint32_t hw = 0, lw = 0;
#pragma unroll
    for (int s = 0; s < 2; s++) {
        float w = W[(kp * 2 + s) * 128 + n];
        __nv_bfloat16 hi = __float2bfloat16(w);
        float rem = w - __bfloat162float(hi);
        __nv_bfloat16 lo = __float2bfloat16(rem);
        hw |= (uint32_t)__bfloat16_as_ushort(hi) << (16 * s);
        lw |= (uint32_t)__bfloat16_as_ushort(lo) << (16 * s);
    }
    g_Bh[layer * 8192 + slot] = hw;
    g_Bl[layer * 8192 + slot] = lw;
}

// ---------------- bf16x3 mma.sync GEMM with fused BN/residual A-load ------
#define MMA_BF16(c, a, b) asm volatile( \
    "mma.sync.aligned.m16n8k16.row.col.f32.bf16.bf16.f32 " \
    "{%0,%1,%2,%3}, {%4,%5,%6,%7}, {%8,%9}, {%0,%1,%2,%3};" \
    : "+f"((c)[0]), "+f"((c)[1]), "+f"((c)[2]), "+f"((c)[3]) \
    : "r"((a)[0]), "r"((a)[1]), "r"((a)[2]), "r"((a)[3]), "r"((b)[0]), "r"((b)[1]))

__global__ void __launch_bounds__(256) k_gemm(int layer, const float* __restrict__ feat,
                                              const float* __restrict__ gamma,
                                              const float* __restrict__ beta) {
    __shared__ uint32_t As_h[128][20];
    __shared__ uint32_t As_l[128][20];
    __shared__ uint32_t Bs_h[128][20];
    __shared__ uint32_t Bs_l[128][20];
    __shared__ float srel[128];
    __shared__ float s_a[128];
    __shared__ float s_sh[128];
    const int tid  = threadIdx.x;
    const int wid  = tid >> 5;
    const int lane = tid & 31;
    const int t    = blockIdx.y;
    const int rb   = blockIdx.x * 128;
    const float* Xsrc = (layer < 2) ? feat : (g_embs + (long)t * ND);
    float* Xwb = g_embs + (long)t * ND;
    const float* Yt = g_Y + (long)t * ND;
    const float* cs = g_csrc + t * NN;
    const uint32_t* Bhb = g_Bh + layer * 8192;
    const uint32_t* Blb = g_Bl + layer * 8192;
    if (tid < 128) {
        srel[tid] = g_rels[t * DD + tid];
        if (layer > 0) {
            float mu  = g_stats[t * 256 + tid] * (1.0f / NN);
            float var = g_stats[t * 256 + 128 + tid] * (1.0f / NN) - mu * mu;
            float a = rsqrtf(var + BN_EPS) * gamma[tid];
            s_a[tid]  = a;
            s_sh[tid] = beta[tid] - mu * a;
        }
    }

    float acc[16][4];
#pragma unroll
    for (int nb = 0; nb < 16; nb++)
#pragma unroll
        for (int j = 0; j < 4; j++) acc[nb][j] = 0.f;

    const int r0 = wid * 16 + (lane >> 2);
    const int kq = lane & 3;

    for (int kc = 0; kc < 4; kc++) {
        __syncthreads();  // also guards srel/s_a/s_sh on first iter
#pragma unroll
        for (int u = 0; u < 4; u++) {
            int slot = tid + u * 256;
            int row  = slot >> 3;
            int c4   = (slot & 7) * 4;
            int grow = rb + row;
            uint32_t h0 = 0, h1 = 0, l0 = 0, l1 = 0;
            if (grow < NN) {
                float c = cs[grow];
                float4 v = *(const float4*)(Xsrc + (long)grow * 128 + kc * 32 + c4);
                if (layer > 0) {   // fused BN + leaky + residual
                    float4 yv = *(const float4*)(Yt + (long)grow * 128 + kc * 32 + c4);
#pragma unroll
                    for (int uu = 0; uu < 4; uu++) {
                        int k = kc * 32 + c4 + uu;
                        float h = (&yv.x)[uu] * s_a[k] + s_sh[k];
                        h = h > 0.f ? h : LSLOPE * h;
                        (&v.x)[uu] += h;
                    }
                    if (layer == 1)
                        *(float4*)(Xwb + (long)grow * 128 + kc * 32 + c4) = v;
                }
                float f[4] = {v.x, v.y, v.z, v.w};
                uint32_t hw[2], lw[2];
#pragma unroll
                for (int jp = 0; jp < 2; jp++) {
                    uint32_t hcur = 0, lcur = 0;
#pragma unroll
                    for (int s = 0; s < 2; s++) {
                        float val = f[jp * 2 + s] * c * srel[kc * 32 + c4 + jp * 2 + s];
                        __nv_bfloat16 hi = __float2bfloat16(val);
                        float rem = val - __bfloat162float(hi);
                        __nv_bfloat16 lo = __float2bfloat16(rem);
                        hcur |= (uint32_t)__bfloat16_as_ushort(hi) << (16 * s);
                        lcur |= (uint32_t)__bfloat16_as_ushort(lo) << (16 * s);
                    }
                    hw[jp] = hcur; lw[jp] = lcur;
                }
                h0 = hw[0]; h1 = hw[1]; l0 = lw[0]; l1 = lw[1];
            }
            int kp = c4 >> 1;
            As_h[row][kp] = h0; As_h[row][kp + 1] = h1;
            As_l[row][kp] = l0; As_l[row][kp + 1] = l1;
        }
#pragma unroll
        for (int u = 0; u < 8; u++) {
            int slot = tid + u * 256;
            int n  = slot >> 4;
            int kp = slot & 15;
            Bs_h[n][kp] = Bhb[n * 64 + kc * 16 + kp];
            Bs_l[n][kp] = Blb[n * 64 + kc * 16 + kp];
        }
        __syncthreads();
#pragma unroll
        for (int s = 0; s < 2; s++) {
            uint32_t ah[4], al[4];
            ah[0] = As_h[r0][s * 8 + kq];
            ah[1] = As_h[r0 + 8][s * 8 + kq];
            ah[2] = As_h[r0][s * 8 + 4 + kq];
            ah[3] = As_h[r0 + 8][s * 8 + 4 + kq];
            al[0] = As_l[r0][s * 8 + kq];
            al[1] = As_l[r0 + 8][s * 8 + kq];
            al[2] = As_l[r0][s * 8 + 4 + kq];
            al[3] = As_l[r0 + 8][s * 8 + 4 + kq];
#pragma unroll
            for (int nb = 0; nb < 16; nb++) {
                int n = nb * 8 + (lane >> 2);
                uint32_t bh[2], bl[2];
                bh[0] = Bs_h[n][s * 8 + kq];
                bh[1] = Bs_h[n][s * 8 + 4 + kq];
                bl[0] = Bs_l[n][s * 8 + kq];
                bl[1] = Bs_l[n][s * 8 + 4 + kq];
                MMA_BF16(acc[nb], ah, bh);
                MMA_BF16(acc[nb], ah, bl);
                MMA_BF16(acc[nb], al, bh);
            }
        }
    }
    int row_a = rb + r0;
    int row_b = row_a + 8;
    int coff  = (lane & 3) * 2;
    __half2* Hh = g_Hh + (long)t * (ND / 2);
#pragma unroll
    for (int nb = 0; nb < 16; nb++) {
        int h2i = (nb * 8 + coff) >> 1;
        if (row_a < NN)
            Hh[(long)row_a * 64 + h2i] = __floats2half2_rn(acc[nb][0], acc[nb][1]);
        if (row_b < NN)
            Hh[(long)row_b * 64 + h2i] = __floats2half2_rn(acc[nb][2], acc[nb][3]);
    }
}

// ---------------- CSR gather (fp16 H), barrier-free warps (MLP=2) ---------
__global__ void __launch_bounds__(256) k_gather(const float* __restrict__ b,
                                                float* ydst) {
    const int t = blockIdx.y;
    int gid  = blockIdx.x * 256 + threadIdx.x;
    int w    = gid >> 5;
    int lane = gid & 31;
    if (w >= NN) return;
    float* ybase = (ydst == nullptr) ? g_Y : ydst;
    const int* csr = g_csr + (long)t * NE;
    const uint2* Hh = (const uint2*)(g_Hh + (long)t * (ND / 2));
    int beg = g_off[t * (NN + 1) + w];
    int end = g_off[t * (NN + 1) + w + 1];
    float4 a0 = make_float4(0.f, 0.f, 0.f, 0.f);
    float4 a1 = make_float4(0.f, 0.f, 0.f, 0.f);
    for (int base = beg; base < end; base += 32) {
        int idx = base + lane;
        int s_l = (idx < end) ? csr[idx] : 0;
        int cnt = min(32, end - base);
        int j = 0;
        for (; j + 1 < cnt; j += 2) {
            int s0 = __shfl_sync(0xffffffffu, s_l, j);
            int s1 = __shfl_sync(0xffffffffu, s_l, j + 1);
            uint2 u0 = Hh[(long)s0 * 32 + lane];
            uint2 u1 = Hh[(long)s1 * 32 + lane];
            float2 f0 = __half22float2(*(__half2*)&u0.x);
            float2 f1 = __half22float2(*(__half2*)&u0.y);
            float2 f2 = __half22float2(*(__half2*)&u1.x);
            float2 f3 = __half22float2(*(__half2*)&u1.y);
            a0.x += f0.x; a0.y += f0.y; a0.z += f1.x; a0.w += f1.y;
            a1.x += f2.x; a1.y += f2.y; a1.z += f3.x; a1.w += f3.y;
        }
        if (j < cnt) {
            int s0 = __shfl_sync(0xffffffffu, s_l, j);
            uint2 u0 = Hh[(long)s0 * 32 + lane];
            float2 f0 = __half22float2(*(__half2*)&u0.x);
            float2 f1 = __half22float2(*(__half2*)&u0.y);
            a0.x += f0.x; a0.y += f0.y; a0.z += f1.x; a0.w += f1.y;
        }
    }
    float cd = g_cdst[t * NN + w];
    float4 bb = *(const float4*)(b + lane * 4);
    float4 r;
    r.x = (a0.x + a1.x) * cd + bb.x;
    r.y = (a0.y + a1.y) * cd + bb.y;
    r.z = (a0.z + a1.z) * cd + bb.z;
    r.w = (a0.w + a1.w) * cd + bb.w;
    *(float4*)(ybase + (long)t * ND + (long)w * 128 + lane * 4) = r;
}

// ---------------- BN column stats over g_Y (batched over types) -----------
__global__ void k_stats() {
    const int t = blockIdx.y;
    const float* Y = g_Y + (long)t * ND;
    int tid  = threadIdx.x;
    int col  = tid & 127;
    int base = blockIdx.x * 256;
    int end  = min(base + 256, NN);
    float s = 0.f, s2 = 0.f;
    for (int r = base + (tid >> 7); r < end; r += 2) {
        float y = Y[(long)r * 128 + col];
        s += y;
        s2 += y * y;
    }
    __shared__ float sh[512];
    sh[tid] = s;
    sh[256 + tid] = s2;
    __syncthreads();
    if (tid < 128) {
        atomicAdd(&g_stats[t * 256 + col],       sh[tid] + sh[tid + 128]);
        atomicAdd(&g_stats[t * 256 + 128 + col], sh[256 + tid] + sh[256 + tid + 128]);
    }
}

// ---------------- relation vector updates ---------------------------------
__global__ void k_relupd(const float* __restrict__ Wr, const float* __restrict__ br) {
    const int t = blockIdx.x;
    __shared__ float sr[128];
    int d = threadIdx.x;
    sr[d] = g_rels[t * DD + d];
    __syncthreads();
    float s = br[d];
#pragma unroll
    for (int k = 0; k < 128; k++) s += sr[k] * Wr[d * 128 + k];
    g_rels[t * DD + d] = s;
}
__global__ void k_relout(const float* __restrict__ Wr, const float* __restrict__ br,
                         float* __restrict__ out) {
    const int t = blockIdx.x;
    __shared__ float sr[128];
    int d = threadIdx.x;
    sr[d] = g_rels[t * DD + d];
    __syncthreads();
    float s = br[d];
#pragma unroll
    for (int k = 0; k < 128; k++) s += sr[k] * Wr[d * 128 + k];
    out[t * DD + d] = s;
}

// ---------------- host orchestration --------------------------------------
extern "C" void kernel_launch(void* const* d_in, const int* in_sizes, int n_in,
                              void* d_out, int out_size) {
    const float* feat = (const float*)d_in[0];
    const float* r0 = (const float*)d_in[1];
    const float* r1 = (const float*)d_in[2];
    const float* r2 = (const float*)d_in[3];
    const float* r3 = (const float*)d_in[4];
    const int* e0 = (const int*)d_in[5];
    const int* e1 = (const int*)d_in[6];
    const int* e2 = (const int*)d_in[7];
    const int* e3 = (const int*)d_in[8];
    const float* gW  = (const float*)d_in[9];
    const float* gb  = (const float*)d_in[10];
    const float* bng = (const float*)d_in[11];
    const float* bnb = (const float*)d_in[12];
    const float* rW  = (const float*)d_in[13];
    const float* rb_ = (const float*)d_in[14];
    float* out = (float*)d_out;

    // setup
    k_zero_hist<<<(4 * NN + 255) / 256, 256>>>();
    k_hist<<<(4 * NE + 255) / 256, 256>>>(e0, e1, e2, e3);
    {
        dim3 g(SCAN_B, 4);
        k_scan1<<<g, 256>>>();
        k_scan2<<<4, 256>>>();
        k_scan3<<<g, 256>>>();
    }
    k_c<<<(4 * NN + 255) / 256, 256>>>();
    k_fill<<<(4 * NE + 255) / 256, 256>>>(e0, e1, e2, e3);
    k_relinit<<<1, 512>>>(r0, r1, r2, r3);
    {
        dim3 g(32, 3);
        k_prepw<<<g, 256>>>(gW);
    }

    const dim3 GEMM_G((NN + 127) / 128, 4);
    const dim3 GATH_G((NN * 32 + 255) / 256, 4);
    const dim3 STAT_G((NN + 255) / 256, 4);

    // conv 0
    k_gemm<<<GEMM_G, 256>>>(0, feat, nullptr, nullptr);
    k_relupd<<<4, 128>>>(rW + 0 * DD * DD, rb_ + 0 * DD);
    k_gather<<<GATH_G, 256>>>(gb + 0 * DD, nullptr);
    k_zero_stats<<<1, 1024>>>();
    k_stats<<<STAT_G, 256>>>();
    // conv 1 (fuses BN0+residual; writes e_new to g_embs)
    k_gemm<<<GEMM_G, 256>>>(1, feat, bng + 0 * DD, bnb + 0 * DD);
    k_relupd<<<4, 128>>>(rW + 1 * DD * DD, rb_ + 1 * DD);
    k_gather<<<GATH_G, 256>>>(gb + 1 * DD, nullptr);
    k_zero_stats<<<1, 1024>>>();
    k_stats<<<STAT_G, 256>>>();
    // conv 2 (fuses BN1+residual; reads g_embs; fp16 H -> gather to out)
    k_gemm<<<GEMM_G, 256>>>(2, feat, bng + 1 * DD, bnb + 1 * DD);
    k_relout<<<4, 128>>>(rW + 2 * DD * DD, rb_ + 2 * DD, out + 4L * ND);
    k_gather<<<GATH_G, 256>>>(gb + 2 * DD, out);
}